// round 7
// baseline (speedup 1.0000x reference)
#include <cuda_runtime.h>
#include <cuda_fp16.h>
#include <cstdint>

// ---------------------------------------------------------------------------
// TractBundle: 3 masked linears (A: 4096->1024 @64 conn, B: 4096->512 @64,
// C: 2048->512 @32), concat last dim. B=8, S=1024 -> 8192 tokens.
// R7: fp16 data path. Pre-kernel converts x to token-paired half2 layout
// (g_x16[(tile*S+c)*32+p] = half2(x[64t+p][c], x[64t+32+p][c])). Prep packs
// metadata as 16B quads {u16 idx[4] (pre-scaled byte offs), half w[4]}.
// Gather: one LDS.32 per connection covers 2 tokens; metadata is 4 wavefronts
// per row-quad instead of 8. fp32 accumulate.
// ---------------------------------------------------------------------------

#define NROWS   2048
#define RQ      24            // quads per row (max 64 conn + slice padding)
#define SLICE   512
#define TPB     256           // 8 warps
#define RPW     16            // rows per warp -> 128 rows per block
#define NGRP    16            // 16 row groups of 128
#define SMEM_BYTES 65536      // x tile: 512 cols * 32 pairs * 4B (also epilogue)

#define XA_OFF  0
#define XB_OFF  16777216u     // 128*4096*32
#define XC_OFF  33554432u
#define X16_TOTAL 41943040u   // + 128*2048*32

__device__ __align__(16) unsigned g_x16[X16_TOTAL];     // half2 per u32, 168MB
__device__ __align__(16) uint4    g_meta[NROWS * RQ];   // {idx16 x4, half w x4}
__device__ __align__(8)  unsigned g_seg[8 * NROWS];     // [slice][row]: qstart | nq<<16

// ---------------------------------------------------------------------------
// Pre-kernel: x (f32, token-major) -> g_x16 (half2 token-paired, col-major
// within 64-token tile). Block: one (tile, 128-col chunk). 256 threads.
// ---------------------------------------------------------------------------
__global__ void __launch_bounds__(256)
xconv_kernel(const float* __restrict__ xa, const float* __restrict__ xb,
             const float* __restrict__ xc)
{
    __shared__ float smf[64 * 129];

    int bx = blockIdx.x;
    const float* x; unsigned dbase; int S, tile, chunk;
    if (bx < 4096)      { x = xa; dbase = XA_OFF; S = 4096; tile = bx >> 5;  chunk = bx & 31; }
    else if (bx < 8192) { x = xb; dbase = XB_OFF; S = 4096; tile = (bx-4096) >> 5; chunk = (bx-4096) & 31; }
    else                { x = xc; dbase = XC_OFF; S = 2048; tile = (bx-8192) >> 4; chunk = (bx-8192) & 15; }

    const int tid  = threadIdx.x;
    const int lane = tid & 31;
    const int warp = tid >> 5;
    const int cb   = chunk * 128;
    const size_t tok0 = (size_t)tile * 64;

    // load 64 tokens x 128 cols, scalar coalesced LDG, conflict-free STS
#pragma unroll
    for (int i = 0; i < 8; i++) {
        int t = warp + 8 * i;
        const float* src = x + (tok0 + t) * S + cb;
#pragma unroll
        for (int j = 0; j < 4; j++)
            smf[t * 129 + lane + 32 * j] = src[lane + 32 * j];
    }
    __syncthreads();

    // pack half2(lo = token p, hi = token p+32) and store coalesced
    unsigned* dst = g_x16 + dbase + ((size_t)tile * S + cb) * 32;
#pragma unroll
    for (int cp = 0; cp < 16; cp++) {
        int c = cp * 8 + warp;
        float lo = smf[lane * 129 + c];
        float hi = smf[(lane + 32) * 129 + c];
        __half2 h = __floats2half2_rn(lo, hi);
        dst[(size_t)c * 32 + lane] = *reinterpret_cast<unsigned*>(&h);
    }
}

// ---------------------------------------------------------------------------
// Prep: one warp per dst row; ballot-compact nonzeros, pack 16B meta quads,
// pad each slice segment to a multiple of 4 entries (idx=0, w=0).
// idx stored pre-scaled: byte offset = col_in_slice * 128 (x smem row pitch).
// ---------------------------------------------------------------------------
__global__ void prep_kernel(const float* __restrict__ wa, const float* __restrict__ ma,
                            const float* __restrict__ wb, const float* __restrict__ mb,
                            const float* __restrict__ wc, const float* __restrict__ mc)
{
    int gw   = (blockIdx.x * blockDim.x + threadIdx.x) >> 5;
    int lane = threadIdx.x & 31;
    if (gw >= NROWS) return;

    const float *w, *m; int nsl;
    if (gw < 1024)      { w = wa + (size_t)gw * 4096;        m = ma + (size_t)gw * 4096;        nsl = 8; }
    else if (gw < 1536) { w = wb + (size_t)(gw-1024) * 4096; m = mb + (size_t)(gw-1024) * 4096; nsl = 8; }
    else                { w = wc + (size_t)(gw-1536) * 2048; m = mc + (size_t)(gw-1536) * 2048; nsl = 4; }

    unsigned short* b16 = (unsigned short*)(g_meta + (size_t)gw * RQ);
    int cnt = 0;
    unsigned ltmask = (1u << lane) - 1u;

    for (int k = 0; k < 8; k++) {
        if (k >= nsl) {
            if (lane == 0) g_seg[k * NROWS + gw] = (unsigned)(cnt >> 2);
            continue;
        }
        int start = cnt;
        for (int c = 0; c < SLICE; c += 32) {
            int   s  = k * SLICE + c + lane;
            float mv = m[s];
            bool  p  = (mv != 0.0f);
            unsigned b = __ballot_sync(0xffffffffu, p);
            if (p) {
                int pos = cnt + __popc(b & ltmask);
                int q = pos >> 2, r = pos & 3;
                b16[q * 8 + r]     = (unsigned short)((c + lane) << 7);   // col*128 bytes
                b16[q * 8 + 4 + r] = __half_as_ushort(__float2half_rn(w[s] * mv));
            }
            cnt += __popc(b);
        }
        int n    = cnt - start;
        int npad = (n + 3) & ~3;
        if (lane < npad - n) {
            int pos = cnt + lane;
            int q = pos >> 2, r = pos & 3;
            b16[q * 8 + r]     = 0;
            b16[q * 8 + 4 + r] = 0;   // half(0)
        }
        cnt = start + npad;
        if (lane == 0)
            g_seg[k * NROWS + gw] = (unsigned)(start >> 2) | ((unsigned)(npad >> 2) << 16);
    }
}

__device__ __forceinline__ uint32_t smem_u32(const void* p) {
    uint32_t a;
    asm("{ .reg .u64 t; cvta.to.shared.u64 t, %1; cvt.u32.u64 %0, t; }" : "=r"(a) : "l"(p));
    return a;
}

// ---------------------------------------------------------------------------
// Gather kernel. Grid: (16 row groups, 128 token tiles of 64) — same-tile
// blocks adjacent so the x16 slice stays hot in L2.
// Block: 256 threads / 8 warps; warp owns 16 rows (8 pairs, fully unrolled).
// Lane p <-> tokens (t0+p, t0+32+p) via half2.
// ---------------------------------------------------------------------------
__global__ void __launch_bounds__(TPB, 2)
gather_kernel(float* __restrict__ out)
{
    extern __shared__ unsigned smx[];

    const int grp  = blockIdx.x;
    const int tile = blockIdx.y;
    const int t0   = tile * 64;

    unsigned xbase_g; int S, nsl, row0g;
    if (grp < 8)       { xbase_g = XA_OFF; S = 4096; nsl = 8; row0g = grp * 128; }
    else if (grp < 12) { xbase_g = XB_OFF; S = 4096; nsl = 8; row0g = 1024 + (grp - 8) * 128; }
    else               { xbase_g = XC_OFF; S = 2048; nsl = 4; row0g = 1536 + (grp - 12) * 128; }

    const int tid    = threadIdx.x;
    const int lane   = tid & 31;
    const int warp   = tid >> 5;
    const int myrow0 = row0g + warp * RPW;

    float accL[RPW], accH[RPW];
#pragma unroll
    for (int r = 0; r < RPW; r++) { accL[r] = 0.0f; accH[r] = 0.0f; }

    const uint32_t xb = smem_u32(smx) + (uint32_t)lane * 4u;

    for (int k = 0; k < nsl; k++) {
        if (k) __syncthreads();

        // --- stage slice: 64KB contiguous half2 tile, 16B cp.async ---
        {
            const unsigned* src = g_x16 + xbase_g + ((size_t)tile * S + k * SLICE) * 32;
            uint32_t dst0 = smem_u32(smx);
#pragma unroll
            for (int i = 0; i < 16; i++) {
                int c = tid + i * 256;
                asm volatile("cp.async.ca.shared.global [%0], [%1], 16;\n"
                             :: "r"(dst0 + (uint32_t)c * 16u), "l"(src + (size_t)c * 4) : "memory");
            }
        }
        asm volatile("cp.async.commit_group;\n" ::: "memory");
        asm volatile("cp.async.wait_group 0;\n" ::: "memory");
        __syncthreads();

        const unsigned* segk = g_seg + k * NROWS + myrow0;

#pragma unroll
        for (int pr = 0; pr < RPW / 2; pr++) {
            int R0 = myrow0 + 2 * pr;
            uint2 sp = __ldg((const uint2*)(segk + 2 * pr));
            int nq0 = (int)(sp.x >> 16);
            int nq1 = (int)(sp.y >> 16);
            const uint4* mp0 = g_meta + (size_t)R0 * RQ + (sp.x & 0xffffu);
            const uint4* mp1 = g_meta + (size_t)(R0 + 1) * RQ + (sp.y & 0xffffu);
            int mq = nq0 > nq1 ? nq0 : nq1;

            uint4 m0 = make_uint4(0,0,0,0), m1 = make_uint4(0,0,0,0);
            if (nq0 > 0) m0 = __ldg(mp0);
            if (nq1 > 0) m1 = __ldg(mp1);

            float l0 = accL[2*pr], h0 = accH[2*pr];
            float l1 = accL[2*pr+1], h1 = accH[2*pr+1];

            for (int q = 0; q < mq; q++) {
                uint4 n0 = m0, n1 = m1;
                if (q + 1 < nq0) n0 = __ldg(mp0 + q + 1);
                if (q + 1 < nq1) n1 = __ldg(mp1 + q + 1);
                if (q < nq0) {
                    uint32_t v0, v1, v2, v3;
                    asm volatile("ld.shared.b32 %0, [%1];" : "=r"(v0) : "r"(xb + (m0.x & 0xffffu)));
                    asm volatile("ld.shared.b32 %0, [%1];" : "=r"(v1) : "r"(xb + (m0.x >> 16)));
                    asm volatile("ld.shared.b32 %0, [%1];" : "=r"(v2) : "r"(xb + (m0.y & 0xffffu)));
                    asm volatile("ld.shared.b32 %0, [%1];" : "=r"(v3) : "r"(xb + (m0.y >> 16)));
                    float2 wA = __half22float2(*reinterpret_cast<__half2*>(&m0.z));
                    float2 wB = __half22float2(*reinterpret_cast<__half2*>(&m0.w));
                    float2 x0 = __half22float2(*reinterpret_cast<__half2*>(&v0));
                    float2 x1 = __half22float2(*reinterpret_cast<__half2*>(&v1));
                    float2 x2 = __half22float2(*reinterpret_cast<__half2*>(&v2));
                    float2 x3 = __half22float2(*reinterpret_cast<__half2*>(&v3));
                    l0 = fmaf(x0.x, wA.x, l0); h0 = fmaf(x0.y, wA.x, h0);
                    l0 = fmaf(x1.x, wA.y, l0); h0 = fmaf(x1.y, wA.y, h0);
                    l0 = fmaf(x2.x, wB.x, l0); h0 = fmaf(x2.y, wB.x, h0);
                    l0 = fmaf(x3.x, wB.y, l0); h0 = fmaf(x3.y, wB.y, h0);
                }
                if (q < nq1) {
                    uint32_t v0, v1, v2, v3;
                    asm volatile("ld.shared.b32 %0, [%1];" : "=r"(v0) : "r"(xb + (m1.x & 0xffffu)));
                    asm volatile("ld.shared.b32 %0, [%1];" : "=r"(v1) : "r"(xb + (m1.x >> 16)));
                    asm volatile("ld.shared.b32 %0, [%1];" : "=r"(v2) : "r"(xb + (m1.y & 0xffffu)));
                    asm volatile("ld.shared.b32 %0, [%1];" : "=r"(v3) : "r"(xb + (m1.y >> 16)));
                    float2 wA = __half22float2(*reinterpret_cast<__half2*>(&m1.z));
                    float2 wB = __half22float2(*reinterpret_cast<__half2*>(&m1.w));
                    float2 x0 = __half22float2(*reinterpret_cast<__half2*>(&v0));
                    float2 x1 = __half22float2(*reinterpret_cast<__half2*>(&v1));
                    float2 x2 = __half22float2(*reinterpret_cast<__half2*>(&v2));
                    float2 x3 = __half22float2(*reinterpret_cast<__half2*>(&v3));
                    l1 = fmaf(x0.x, wA.x, l1); h1 = fmaf(x0.y, wA.x, h1);
                    l1 = fmaf(x1.x, wA.y, l1); h1 = fmaf(x1.y, wA.y, h1);
                    l1 = fmaf(x2.x, wB.x, l1); h1 = fmaf(x2.y, wB.x, h1);
                    l1 = fmaf(x3.x, wB.y, l1); h1 = fmaf(x3.y, wB.y, h1);
                }
                m0 = n0; m1 = n1;
            }
            accL[2*pr] = l0;   accH[2*pr] = h0;
            accL[2*pr+1] = l1; accH[2*pr+1] = h1;
        }
    }

    // --- epilogue: per-warp transpose (32 tokens x 16 rows) -> STG ---
    __syncthreads();
    float* tw = (float*)smx + warp * (32 * 17);
#pragma unroll
    for (int r = 0; r < RPW; r++) tw[lane * 17 + r] = accL[r];
    __syncwarp();
#pragma unroll
    for (int tt = 0; tt < 32; tt++)
        if (lane < RPW)
            out[(size_t)(t0 + tt) * 2048 + myrow0 + lane] = tw[tt * 17 + lane];
    __syncwarp();
#pragma unroll
    for (int r = 0; r < RPW; r++) tw[lane * 17 + r] = accH[r];
    __syncwarp();
#pragma unroll
    for (int tt = 0; tt < 32; tt++)
        if (lane < RPW)
            out[(size_t)(t0 + 32 + tt) * 2048 + myrow0 + lane] = tw[tt * 17 + lane];
}

// ---------------------------------------------------------------------------
extern "C" void kernel_launch(void* const* d_in, const int* in_sizes, int n_in,
                              void* d_out, int out_size)
{
    const float *x_a, *w_a, *m_a, *x_b, *w_b, *m_b, *x_c, *w_c, *m_c;
    if (n_in >= 9 && in_sizes[1] == 4194304) {
        x_a = (const float*)d_in[0]; w_a = (const float*)d_in[1]; m_a = (const float*)d_in[2];
        x_b = (const float*)d_in[3]; w_b = (const float*)d_in[4]; m_b = (const float*)d_in[5];
        x_c = (const float*)d_in[6]; w_c = (const float*)d_in[7]; m_c = (const float*)d_in[8];
    } else {
        x_a = (const float*)d_in[0]; x_b = (const float*)d_in[1]; x_c = (const float*)d_in[2];
        w_a = (const float*)d_in[3]; w_b = (const float*)d_in[4]; w_c = (const float*)d_in[5];
        m_a = (const float*)d_in[6]; m_b = (const float*)d_in[7]; m_c = (const float*)d_in[8];
    }

    float* out = (float*)d_out;

    static int attr_done = 0;
    if (!attr_done) {
        cudaFuncSetAttribute(gather_kernel, cudaFuncAttributeMaxDynamicSharedMemorySize, SMEM_BYTES);
        attr_done = 1;
    }

    xconv_kernel<<<10240, 256>>>(x_a, x_b, x_c);
    prep_kernel<<<NROWS / 8, 256>>>(w_a, m_a, w_b, m_b, w_c, m_c);

    dim3 grid(NGRP, 128);
    gather_kernel<<<grid, TPB, SMEM_BYTES>>>(out);
}

// round 9
// speedup vs baseline: 2.4830x; 2.4830x over previous
#include <cuda_runtime.h>
#include <cuda_fp16.h>
#include <cstdint>

// ---------------------------------------------------------------------------
// TractBundle via dense fp16 GEMM (fp32 accumulate).
//   out[:, 0:1024]    = x_a @ (w_a*m_a)^T   (K=4096)
//   out[:, 1024:1536] = x_b @ (w_b*m_b)^T   (K=4096)
//   out[:, 1536:2048] = x_c @ (w_c*m_c)^T   (K=2048)
// Mask zeros are exact in fp16 -> dense == sparse; fp16 input rounding gives
// ~3e-4 rel err (measured R7), under the 1e-3 gate.
//
// DUAL COMPILE PATH: the harness emits a generic compute_103 PTX pass where
// tcgen05 is illegal. tcgen05 path is guarded by the arch-specific feature
// macros; otherwise an mma.sync.m16n8k16 (sm_80-class HMMA) path compiles.
// Both share: job decode, K-chunk-64 cp.async double buffer, SW128 swizzle.
// ---------------------------------------------------------------------------

#define TPB 256

#if defined(__CUDA_ARCH_FEAT_SM103_ALL) || defined(__CUDA_ARCH_FEAT_SM100_ALL) || \
    (defined(__CUDA_ARCH_SPECIFIC__) && (__CUDA_ARCH_SPECIFIC__ >= 1000))
#define HAS_TCGEN05 1
#else
#define HAS_TCGEN05 0
#endif

// fp16 operand storage (device globals; no allocation allowed)
__device__ __align__(16) __half g_xh[83886080];  // a@0, b@33554432, c@67108864
__device__ __align__(16) __half g_wh[7340032];   // a@0, b@4194304,  c@6291456

// idesc kind::f16: dtype f32 (1<<4), atype/btype f16 (0), N=256 (32<<17), M=128 (8<<24)
#define GEMM_IDESC 0x08400010u
// SW128 K-major smem descriptor base (version=1, SBO=64, LBO=1, layout=SW128)
#define SMEM_DESC_BASE ((2ull << 61) | (1ull << 46) | (64ull << 32) | (1ull << 16))

// smem layout relative to 1024B-aligned base:
// tcgen05: [0..4) tmem ptr, [8..24) mbarriers; A stages @1024,17408; B @33792,66560
// mma.sync: A stages @1024,17408 (128x128B); B-half stages @33792,50176 (128x128B)
#define SM_A0   1024u
#define SM_A1   17408u
#define SM_B0   33792u
#define SM_B1   66560u
#define SM_FB_B0 33792u
#define SM_FB_B1 50176u
#define SMEM_BYTES (1024 + 99328)

// ---------------------------------------------------------------------------
__global__ void __launch_bounds__(256)
f2h_kernel(const float* __restrict__ src, __half* __restrict__ dst, int n4)
{
    int i = blockIdx.x * blockDim.x + threadIdx.x;
    if (i < n4) {
        float4 v = ((const float4*)src)[i];
        __half2* d = (__half2*)dst + (size_t)i * 2;
        d[0] = __floats2half2_rn(v.x, v.y);
        d[1] = __floats2half2_rn(v.z, v.w);
    }
}

__global__ void __launch_bounds__(256)
wm2h_kernel(const float* __restrict__ w, const float* __restrict__ m,
            __half* __restrict__ dst, int n4)
{
    int i = blockIdx.x * blockDim.x + threadIdx.x;
    if (i < n4) {
        float4 wv = ((const float4*)w)[i];
        float4 mv = ((const float4*)m)[i];
        __half2* d = (__half2*)dst + (size_t)i * 2;
        d[0] = __floats2half2_rn(wv.x * mv.x, wv.y * mv.y);
        d[1] = __floats2half2_rn(wv.z * mv.z, wv.w * mv.w);
    }
}

// ---------------------------------------------------------------------------
__device__ __forceinline__ uint32_t smem_u32(const void* p) {
    uint32_t a;
    asm("{ .reg .u64 t; cvta.to.shared.u64 t, %1; cvt.u32.u64 %0, t; }" : "=r"(a) : "l"(p));
    return a;
}

#if HAS_TCGEN05
__device__ __forceinline__ uint32_t elect1() {
    uint32_t r;
    asm volatile("{ .reg .pred p; elect.sync _|p, 0xFFFFFFFF; selp.b32 %0, 1, 0, p; }" : "=r"(r));
    return r;
}
__device__ __forceinline__ void mbar_wait(uint32_t addr, int phase) {
    asm volatile(
        "{\n\t.reg .pred P;\n"
        "WL_%=:\n\t"
        "mbarrier.try_wait.parity.acquire.cta.shared::cta.b64 P, [%0], %1, 0x989680;\n\t"
        "@P bra.uni WD_%=;\n\t"
        "bra.uni WL_%=;\n"
        "WD_%=:\n\t}\n"
        :: "r"(addr), "r"((uint32_t)phase) : "memory");
}
#endif

// ---------------------------------------------------------------------------
// GEMM kernel: 512 jobs. Tile: M=128 tokens x N=256 out-cols, K chunks of 64.
// ---------------------------------------------------------------------------
__global__ void __launch_bounds__(TPB, 1)
gemm_kernel(float* __restrict__ out)
{
    extern __shared__ char dsm[];
    const uint32_t base = (smem_u32(dsm) + 1023u) & ~1023u;
    const int tid  = threadIdx.x;
    const int lane = tid & 31;
    const int warp = tid >> 5;

    // ---- job decode ----
    int j = blockIdx.x;
    const __half *xh, *wh; int K, outb, mt, nt;
    if (j < 256)      { int q = j;       nt = q >> 6; mt = q & 63; xh = g_xh;            wh = g_wh;           K = 4096; outb = nt * 256; }
    else if (j < 384) { int q = j - 256; nt = q >> 6; mt = q & 63; xh = g_xh + 33554432; wh = g_wh + 4194304; K = 4096; outb = 1024 + nt * 256; }
    else              { int q = j - 384; nt = q >> 6; mt = q & 63; xh = g_xh + 67108864; wh = g_wh + 6291456; K = 2048; outb = 1536 + nt * 256; }
    const int nc   = K >> 6;
    const int tok0 = mt * 128;
    const __half* asrc = xh + (size_t)tok0 * K;

#if HAS_TCGEN05
    // ======================= tcgen05 path ==================================
    const uint32_t mbar0 = base + 8u;
    const uint32_t smA[2] = { base + SM_A0, base + SM_A1 };
    const uint32_t smB[2] = { base + SM_B0, base + SM_B1 };
    const __half* bsrc = wh + (size_t)(nt * 256) * K;

    if (warp == 0) {
        asm volatile("tcgen05.alloc.cta_group::1.sync.aligned.shared::cta.b32 [%0], %1;"
                     :: "r"(base), "r"(256) : "memory");
        asm volatile("tcgen05.relinquish_alloc_permit.cta_group::1.sync.aligned;");
    }
    if (tid == 0) {
        asm volatile("mbarrier.init.shared.b64 [%0], %1;" :: "r"(mbar0),      "r"(1) : "memory");
        asm volatile("mbarrier.init.shared.b64 [%0], %1;" :: "r"(mbar0 + 8u), "r"(1) : "memory");
    }
    __syncthreads();
    uint32_t tmem;
    asm volatile("ld.shared.b32 %0, [%1];" : "=r"(tmem) : "r"(base));

    auto stage = [&](int c, int s) {
        const __half* ap = asrc + (c << 6);
        const __half* bp = bsrc + (c << 6);
#pragma unroll
        for (int i = 0; i < 4; i++) {
            int o = tid + (i << 8);
            int row = o >> 3, seg = o & 7;
            uint32_t off = (uint32_t)(row << 7) + (uint32_t)(seg << 4);
            uint32_t sw  = off ^ ((off >> 3) & 0x70u);
            asm volatile("cp.async.cg.shared.global [%0], [%1], 16;\n"
                         :: "r"(smA[s] + sw), "l"(ap + (size_t)row * K + (seg << 3)) : "memory");
        }
#pragma unroll
        for (int i = 0; i < 8; i++) {
            int o = tid + (i << 8);
            int row = o >> 3, seg = o & 7;
            uint32_t off = (uint32_t)(row << 7) + (uint32_t)(seg << 4);
            uint32_t sw  = off ^ ((off >> 3) & 0x70u);
            asm volatile("cp.async.cg.shared.global [%0], [%1], 16;\n"
                         :: "r"(smB[s] + sw), "l"(bp + (size_t)row * K + (seg << 3)) : "memory");
        }
        asm volatile("cp.async.commit_group;\n" ::: "memory");
    };

    stage(0, 0);
    stage(1, 1);
    int ph0 = 0, ph1 = 0;

    for (int c = 0; c < nc; c++) {
        int s = c & 1;
        if (c == nc - 1) asm volatile("cp.async.wait_group 0;\n" ::: "memory");
        else             asm volatile("cp.async.wait_group 1;\n" ::: "memory");
        __syncthreads();

        if (warp == 0 && elect1()) {
            uint64_t ad = SMEM_DESC_BASE | ((uint64_t)(smA[s] >> 4) & 0x3FFFull);
            uint64_t bd = SMEM_DESC_BASE | ((uint64_t)(smB[s] >> 4) & 0x3FFFull);
#pragma unroll
            for (int kk = 0; kk < 4; kk++) {
                uint32_t en = (c | kk) ? 1u : 0u;
                asm volatile(
                    "{\n\t.reg .pred p;\n\t"
                    "setp.ne.u32 p, %4, 0;\n\t"
                    "tcgen05.mma.cta_group::1.kind::f16 [%0], %1, %2, %3, {%5, %5, %5, %5}, p;\n\t}"
                    :: "r"(tmem), "l"(ad + kk * 2), "l"(bd + kk * 2),
                       "r"(GEMM_IDESC), "r"(en), "r"(0u) : "memory");
            }
            asm volatile("tcgen05.commit.cta_group::1.mbarrier::arrive::one.shared::cluster.b64 [%0];"
                         :: "r"(mbar0 + (uint32_t)s * 8u) : "memory");
        }

        if (c + 2 < nc) {
            if (s == 0) { mbar_wait(mbar0, ph0);      ph0 ^= 1; }
            else        { mbar_wait(mbar0 + 8u, ph1); ph1 ^= 1; }
            stage(c + 2, s);
        }
    }
    {
        int s = nc & 1;
        if (s == 0) { mbar_wait(mbar0, ph0);      ph0 ^= 1; }
        else        { mbar_wait(mbar0 + 8u, ph1); ph1 ^= 1; }
        s = (nc - 1) & 1;
        if (s == 0) { mbar_wait(mbar0, ph0);      ph0 ^= 1; }
        else        { mbar_wait(mbar0 + 8u, ph1); ph1 ^= 1; }
    }
    asm volatile("tcgen05.fence::after_thread_sync;" ::: "memory");

    if (warp < 4) {
        float* orow = out + (size_t)(tok0 + (warp << 5) + lane) * 2048 + outb;
#pragma unroll
        for (int cb = 0; cb < 256; cb += 32) {
            uint32_t r[32];
            asm volatile(
                "tcgen05.ld.sync.aligned.32x32b.x32.b32 "
                "{%0,%1,%2,%3,%4,%5,%6,%7,%8,%9,%10,%11,%12,%13,%14,%15,"
                "%16,%17,%18,%19,%20,%21,%22,%23,%24,%25,%26,%27,%28,%29,%30,%31}, [%32];"
                : "=r"(r[0]),"=r"(r[1]),"=r"(r[2]),"=r"(r[3]),"=r"(r[4]),"=r"(r[5]),"=r"(r[6]),"=r"(r[7]),
                  "=r"(r[8]),"=r"(r[9]),"=r"(r[10]),"=r"(r[11]),"=r"(r[12]),"=r"(r[13]),"=r"(r[14]),"=r"(r[15]),
                  "=r"(r[16]),"=r"(r[17]),"=r"(r[18]),"=r"(r[19]),"=r"(r[20]),"=r"(r[21]),"=r"(r[22]),"=r"(r[23]),
                  "=r"(r[24]),"=r"(r[25]),"=r"(r[26]),"=r"(r[27]),"=r"(r[28]),"=r"(r[29]),"=r"(r[30]),"=r"(r[31])
                : "r"(tmem + (uint32_t)cb));
            asm volatile("tcgen05.wait::ld.sync.aligned;" ::: "memory");
#pragma unroll
            for (int q = 0; q < 8; q++) {
                float4 v;
                v.x = __uint_as_float(r[q * 4 + 0]);
                v.y = __uint_as_float(r[q * 4 + 1]);
                v.z = __uint_as_float(r[q * 4 + 2]);
                v.w = __uint_as_float(r[q * 4 + 3]);
                *(float4*)(orow + cb + q * 4) = v;
            }
        }
        asm volatile("tcgen05.fence::before_thread_sync;" ::: "memory");
    }

    __syncthreads();
    if (tid == 0) {
        asm volatile("mbarrier.inval.shared.b64 [%0];" :: "r"(mbar0) : "memory");
        asm volatile("mbarrier.inval.shared.b64 [%0];" :: "r"(mbar0 + 8u) : "memory");
    }
    __syncthreads();
    if (warp == 0) {
        asm volatile("tcgen05.dealloc.cta_group::1.sync.aligned.b32 %0, %1;"
                     :: "r"(tmem), "r"(256));
    }

#else
    // ======================= mma.sync fallback path =========================
    // 8 warps tile 128x128 per n-pass (2 passes). warp_m = warp&1 (64 rows),
    // warp_n = warp>>1 (32 cols). Per warp: 4 m16 x 4 n8 mma tiles.
    const uint32_t smA[2] = { base + SM_A0,    base + SM_A1 };
    const uint32_t smB[2] = { base + SM_FB_B0, base + SM_FB_B1 };
    const int warp_m = warp & 1;
    const int warp_n = warp >> 1;

    for (int pass = 0; pass < 2; pass++) {
        const __half* bsrc = wh + (size_t)(nt * 256 + pass * 128) * K;

        auto stage = [&](int c, int s) {
            const __half* ap = asrc + (c << 6);
            const __half* bp = bsrc + (c << 6);
#pragma unroll
            for (int i = 0; i < 4; i++) {
                int o = tid + (i << 8);
                int row = o >> 3, seg = o & 7;
                uint32_t off = (uint32_t)(row << 7) + (uint32_t)(seg << 4);
                uint32_t sw  = off ^ ((off >> 3) & 0x70u);
                asm volatile("cp.async.cg.shared.global [%0], [%1], 16;\n"
                             :: "r"(smA[s] + sw), "l"(ap + (size_t)row * K + (seg << 3)) : "memory");
            }
#pragma unroll
            for (int i = 0; i < 4; i++) {
                int o = tid + (i << 8);
                int row = o >> 3, seg = o & 7;
                uint32_t off = (uint32_t)(row << 7) + (uint32_t)(seg << 4);
                uint32_t sw  = off ^ ((off >> 3) & 0x70u);
                asm volatile("cp.async.cg.shared.global [%0], [%1], 16;\n"
                             :: "r"(smB[s] + sw), "l"(bp + (size_t)row * K + (seg << 3)) : "memory");
            }
            asm volatile("cp.async.commit_group;\n" ::: "memory");
        };

        float c4[4][4][4];
#pragma unroll
        for (int a = 0; a < 4; a++)
#pragma unroll
            for (int b = 0; b < 4; b++)
#pragma unroll
                for (int e = 0; e < 4; e++) c4[a][b][e] = 0.0f;

        stage(0, 0);
        stage(1, 1);

        for (int c = 0; c < nc; c++) {
            int s = c & 1;
            if (c == nc - 1) asm volatile("cp.async.wait_group 0;\n" ::: "memory");
            else             asm volatile("cp.async.wait_group 1;\n" ::: "memory");
            __syncthreads();

#pragma unroll
            for (int kk = 0; kk < 4; kk++) {
                uint32_t A[4][4];
#pragma unroll
                for (int mti = 0; mti < 4; mti++) {
                    uint32_t off = (uint32_t)((warp_m * 64 + mti * 16 + (lane & 15)) << 7)
                                 + (uint32_t)(kk << 5) + (uint32_t)((lane >> 4) << 4);
                    uint32_t sw = off ^ ((off >> 3) & 0x70u);
                    asm volatile("ldmatrix.sync.aligned.m8n8.x4.shared.b16 {%0,%1,%2,%3}, [%4];"
                                 : "=r"(A[mti][0]), "=r"(A[mti][1]), "=r"(A[mti][2]), "=r"(A[mti][3])
                                 : "r"(smA[s] + sw));
                }
                uint32_t B[2][4];
#pragma unroll
                for (int ng = 0; ng < 2; ng++) {
                    uint32_t nrow = (uint32_t)(warp_n * 32 + ng * 16 + (lane & 7) + ((lane & 16) >> 1));
                    uint32_t off = (nrow << 7) + (uint32_t)(kk << 5) + (uint32_t)(((lane >> 3) & 1) << 4);
                    uint32_t sw = off ^ ((off >> 3) & 0x70u);
                    asm volatile("ldmatrix.sync.aligned.m8n8.x4.shared.b16 {%0,%1,%2,%3}, [%4];"
                                 : "=r"(B[ng][0]), "=r"(B[ng][1]), "=r"(B[ng][2]), "=r"(B[ng][3])
                                 : "r"(smB[s] + sw));
                }
#pragma unroll
                for (int mti = 0; mti < 4; mti++)
#pragma unroll
                    for (int nti = 0; nti < 4; nti++) {
                        int ng = nti >> 1, jh = nti & 1;
                        asm volatile(
                            "mma.sync.aligned.m16n8k16.row.col.f32.f16.f16.f32 "
                            "{%0,%1,%2,%3}, {%4,%5,%6,%7}, {%8,%9}, {%0,%1,%2,%3};"
                            : "+f"(c4[mti][nti][0]), "+f"(c4[mti][nti][1]),
                              "+f"(c4[mti][nti][2]), "+f"(c4[mti][nti][3])
                            : "r"(A[mti][0]), "r"(A[mti][1]), "r"(A[mti][2]), "r"(A[mti][3]),
                              "r"(B[ng][2 * jh]), "r"(B[ng][2 * jh + 1]));
                    }
            }
            __syncthreads();
            if (c + 2 < nc) stage(c + 2, s);
        }

        // epilogue: direct float2 stores
#pragma unroll
        for (int mti = 0; mti < 4; mti++) {
            size_t mrow = (size_t)(tok0 + warp_m * 64 + mti * 16 + (lane >> 2));
#pragma unroll
            for (int nti = 0; nti < 4; nti++) {
                int col = outb + pass * 128 + warp_n * 32 + nti * 8 + (lane & 3) * 2;
                *(float2*)(out + mrow * 2048 + col) =
                    make_float2(c4[mti][nti][0], c4[mti][nti][1]);
                *(float2*)(out + (mrow + 8) * 2048 + col) =
                    make_float2(c4[mti][nti][2], c4[mti][nti][3]);
            }
        }
        __syncthreads();   // smem stages reused by next pass
    }
#endif
}

// ---------------------------------------------------------------------------
extern "C" void kernel_launch(void* const* d_in, const int* in_sizes, int n_in,
                              void* d_out, int out_size)
{
    const float *x_a, *w_a, *m_a, *x_b, *w_b, *m_b, *x_c, *w_c, *m_c;
    if (n_in >= 9 && in_sizes[1] == 4194304) {
        x_a = (const float*)d_in[0]; w_a = (const float*)d_in[1]; m_a = (const float*)d_in[2];
        x_b = (const float*)d_in[3]; w_b = (const float*)d_in[4]; m_b = (const float*)d_in[5];
        x_c = (const float*)d_in[6]; w_c = (const float*)d_in[7]; m_c = (const float*)d_in[8];
    } else {
        x_a = (const float*)d_in[0]; x_b = (const float*)d_in[1]; x_c = (const float*)d_in[2];
        w_a = (const float*)d_in[3]; w_b = (const float*)d_in[4]; w_c = (const float*)d_in[5];
        m_a = (const float*)d_in[6]; m_b = (const float*)d_in[7]; m_c = (const float*)d_in[8];
    }

    float* out = (float*)d_out;

    static int attr_done = 0;
    if (!attr_done) {
        cudaFuncSetAttribute(gemm_kernel, cudaFuncAttributeMaxDynamicSharedMemorySize, SMEM_BYTES);
        attr_done = 1;
    }

    __half* xh; cudaGetSymbolAddress((void**)&xh, g_xh);
    __half* wh; cudaGetSymbolAddress((void**)&wh, g_wh);

    f2h_kernel<<<32768, 256>>>(x_a, xh,            8388608);
    f2h_kernel<<<32768, 256>>>(x_b, xh + 33554432, 8388608);
    f2h_kernel<<<16384, 256>>>(x_c, xh + 67108864, 4194304);
    wm2h_kernel<<<4096, 256>>>(w_a, m_a, wh,           1048576);
    wm2h_kernel<<<2048, 256>>>(w_b, m_b, wh + 4194304,  524288);
    wm2h_kernel<<<1024, 256>>>(w_c, m_c, wh + 6291456,  262144);

    gemm_kernel<<<512, TPB, SMEM_BYTES>>>(out);
}